// round 1
// baseline (speedup 1.0000x reference)
#include <cuda_runtime.h>
#include <math.h>

#define NB 16
#define CIN 256
#define TT 4096
#define M2 512
#define CC 256
#define PP 32
#define LL 4098
#define LPAD 4110

// ---------------- scratch (__device__ globals; no allocation) ----------------
__device__ float g_Wf[M2 * CIN];      // folded conv1 weights, rows interleaved (a,g) per channel
__device__ float g_bf[M2];
__device__ float g_w0[PP * 62];       // folded p0 weights [co][ci(2)][k(31)]
__device__ float g_b0[PP];
__device__ float g_w1f[PP * PP * 15]; // folded p1 weights
__device__ float g_b1f[PP];
__device__ float g_feat[NB * TT * CC];   // (b,t,c) fp32
__device__ float g_xx[NB * TT];
__device__ float g_h1[NB * PP * TT];
__device__ float g_h2[NB * PP * TT];
__device__ float g_jmp[NB * 2 * TT];
__device__ float g_c1[NB * TT];
__device__ float g_c2[NB * TT];
__device__ int   g_S[NB * 4100];         // S[p] = first t with fi[t] >= p
__device__ float g_out2[NB * LL * CC];   // (b,p,c) before transpose

// ---------------- K0: fold BN into conv weights ----------------
__global__ void k_fold(const float* cw, const float* g1, const float* b1,
                       const float* m1, const float* v1,
                       const float* p0w, const float* p0b, const float* p0g,
                       const float* p0bb, const float* p0m, const float* p0v,
                       const float* p1w, const float* p1b, const float* p1g,
                       const float* p1bb, const float* p1m, const float* p1v) {
    int tid = threadIdx.x;
    if (tid < M2) {
        float s = g1[tid] * rsqrtf(v1[tid] + 1e-3f);
        int mp = (tid < CC) ? 2 * tid : 2 * (tid - CC) + 1;
        for (int k = 0; k < CIN; k++) g_Wf[mp * CIN + k] = cw[tid * CIN + k] * s;
        g_bf[mp] = b1[tid] - m1[tid] * s;
    }
    if (tid < PP) {
        float s0 = p0g[tid] * rsqrtf(p0v[tid] + 1e-5f);
        for (int j = 0; j < 62; j++) g_w0[tid * 62 + j] = p0w[tid * 62 + j] * s0;
        g_b0[tid] = (p0b[tid] - p0m[tid]) * s0 + p0bb[tid];
        float s1 = p1g[tid] * rsqrtf(p1v[tid] + 1e-5f);
        for (int j = 0; j < PP * 15; j++)
            g_w1f[tid * PP * 15 + j] = p1w[tid * PP * 15 + j] * s1;
        g_b1f[tid] = (p1b[tid] - p1m[tid]) * s1 + p1bb[tid];
    }
}

// ---------------- K1: SGEMM (conv1) + BN + GLU + fused xx ----------------
// Tile: BM=128 (of 512 interleaved rows), BN=64 t, BK=16. 256 threads, 8x4 per thread.
__global__ __launch_bounds__(256) void k_gemm(const float* __restrict__ x,
                                              const float* __restrict__ w1x1) {
    __shared__ __align__(16) float Ws[2][16][128];
    __shared__ __align__(16) float Xs[2][16][64];
    __shared__ __align__(16) float ep[64][68];

    int tid = threadIdx.x;
    int tx = tid & 15, ty = tid >> 4;
    int n0 = blockIdx.x * 64;
    int b = n0 >> 12, t0 = n0 & (TT - 1);
    int m0 = blockIdx.y * 128;
    bool doxx = (blockIdx.y == 0) && (tid < 64);

    float acc[8][4];
#pragma unroll
    for (int i = 0; i < 8; i++)
#pragma unroll
        for (int n = 0; n < 4; n++) acc[i][n] = 0.f;
    float xxa = 0.f;

    // load tile 0
    {
#pragma unroll
        for (int i = 0; i < 2; i++) {
            int li = tid + i * 256;
            int m = li >> 2, kq = li & 3;
            float4 wv = *(const float4*)&g_Wf[(m0 + m) * CIN + kq * 4];
            Ws[0][kq * 4 + 0][m] = wv.x; Ws[0][kq * 4 + 1][m] = wv.y;
            Ws[0][kq * 4 + 2][m] = wv.z; Ws[0][kq * 4 + 3][m] = wv.w;
        }
        int row = tid >> 4, col = tid & 15;
        float4 xv = *(const float4*)&x[((size_t)b * CIN + row) * TT + t0 + col * 4];
        *(float4*)&Xs[0][row][col * 4] = xv;
    }
    __syncthreads();

    int buf = 0;
    for (int kt = 0; kt < 16; ++kt) {
        float4 wpre[2]; float4 xpre;
        if (kt < 15) {
            int k0 = (kt + 1) * 16;
#pragma unroll
            for (int i = 0; i < 2; i++) {
                int li = tid + i * 256;
                int m = li >> 2, kq = li & 3;
                wpre[i] = *(const float4*)&g_Wf[(m0 + m) * CIN + k0 + kq * 4];
            }
            int row = tid >> 4, col = tid & 15;
            xpre = *(const float4*)&x[((size_t)b * CIN + k0 + row) * TT + t0 + col * 4];
        }
#pragma unroll
        for (int kk = 0; kk < 16; ++kk) {
            float4 xv = *(float4*)&Xs[buf][kk][tx * 4];
            float4 wa = *(float4*)&Ws[buf][kk][ty * 8];
            float4 wb = *(float4*)&Ws[buf][kk][ty * 8 + 4];
            float wr[8] = {wa.x, wa.y, wa.z, wa.w, wb.x, wb.y, wb.z, wb.w};
            float xr[4] = {xv.x, xv.y, xv.z, xv.w};
#pragma unroll
            for (int i = 0; i < 8; i++)
#pragma unroll
                for (int n = 0; n < 4; n++) acc[i][n] += wr[i] * xr[n];
        }
        if (doxx) {
#pragma unroll
            for (int kk = 0; kk < 16; ++kk)
                xxa += __ldg(&w1x1[kt * 16 + kk]) * Xs[buf][kk][tid];
        }
        if (kt < 15) {
            int nb = buf ^ 1;
#pragma unroll
            for (int i = 0; i < 2; i++) {
                int li = tid + i * 256;
                int m = li >> 2, kq = li & 3;
                Ws[nb][kq * 4 + 0][m] = wpre[i].x; Ws[nb][kq * 4 + 1][m] = wpre[i].y;
                Ws[nb][kq * 4 + 2][m] = wpre[i].z; Ws[nb][kq * 4 + 3][m] = wpre[i].w;
            }
            int row = tid >> 4, col = tid & 15;
            *(float4*)&Xs[nb][row][col * 4] = xpre;
            __syncthreads();
            buf = nb;
        }
    }

    // epilogue: bias + GLU, stage through smem for coalesced (b,t,c) writes
#pragma unroll
    for (int j = 0; j < 4; j++) {
        int mA = m0 + ty * 8 + 2 * j;
        float ba = g_bf[mA], bg = g_bf[mA + 1];
#pragma unroll
        for (int n = 0; n < 4; n++) {
            float a = acc[2 * j][n] + ba;
            float g = acc[2 * j + 1][n] + bg;
            ep[tx * 4 + n][ty * 4 + j] = a / (1.f + expf(-g));
        }
    }
    if (doxx) g_xx[b * TT + t0 + tid] = xxa;
    __syncthreads();
    {
        int c4 = tid & 15, tyy = tid >> 4;
#pragma unroll
        for (int r = 0; r < 4; r++) {
            int tl = tyy + r * 16;
            float4 v = *(float4*)&ep[tl][c4 * 4];
            *(float4*)&g_feat[((size_t)(b * TT + t0 + tl)) * CC + blockIdx.y * 64 + c4 * 4] = v;
        }
    }
}

// ---------------- K2a: predictor p0 conv + BN + silu ----------------
__global__ __launch_bounds__(256) void k_p0() {
    int b = blockIdx.y, t0 = blockIdx.x * 256, tid = threadIdx.x;
    __shared__ float xs[286], x2s[286];
    __shared__ float w0s[PP * 62];
    __shared__ float b0s[PP];
    for (int i = tid; i < 286; i += 256) {
        int gt = t0 - 15 + i;
        float v = (gt >= 0 && gt < TT) ? g_xx[b * TT + gt] : 0.f;
        xs[i] = v; x2s[i] = v * v;
    }
    for (int i = tid; i < PP * 62; i += 256) w0s[i] = g_w0[i];
    if (tid < PP) b0s[tid] = g_b0[tid];
    __syncthreads();
    float xr[31], x2r[31];
#pragma unroll
    for (int i = 0; i < 31; i++) { xr[i] = xs[tid + i]; x2r[i] = x2s[tid + i]; }
    for (int co = 0; co < PP; ++co) {
        float a = b0s[co];
#pragma unroll
        for (int k = 0; k < 31; k++)
            a += w0s[co * 62 + k] * xr[k] + w0s[co * 62 + 31 + k] * x2r[k];
        a = a / (1.f + expf(-a));
        g_h1[(b * PP + co) * TT + t0 + tid] = a;
    }
}

// ---------------- K2b: predictor p1 conv + BN + silu ----------------
__global__ __launch_bounds__(256) void k_p1() {
    int b = blockIdx.y, t0 = blockIdx.x * 128, tid = threadIdx.x;
    int cog = tid >> 5, tl = tid & 31;
    __shared__ float hs[PP][144];
    for (int i = tid; i < PP * 142; i += 256) {
        int ci = i / 142, tt = i % 142;
        int gt = t0 - 7 + tt;
        hs[ci][tt] = (gt >= 0 && gt < TT) ? g_h1[(b * PP + ci) * TT + gt] : 0.f;
    }
    __syncthreads();
    float acc[4][4];
#pragma unroll
    for (int j = 0; j < 4; j++) {
        float bb = g_b1f[cog * 4 + j];
#pragma unroll
        for (int n = 0; n < 4; n++) acc[j][n] = bb;
    }
    for (int ci = 0; ci < PP; ++ci) {
        float hr[18];
#pragma unroll
        for (int i = 0; i < 18; i++) hr[i] = hs[ci][tl * 4 + i];
#pragma unroll
        for (int k = 0; k < 15; k++) {
#pragma unroll
            for (int j = 0; j < 4; j++) {
                float w = g_w1f[(cog * 4 + j) * 480 + ci * 15 + k];
#pragma unroll
                for (int n = 0; n < 4; n++) acc[j][n] += w * hr[k + n];
            }
        }
    }
#pragma unroll
    for (int j = 0; j < 4; j++) {
        int co = cog * 4 + j;
#pragma unroll
        for (int n = 0; n < 4; n++) {
            float v = acc[j][n];
            v = v / (1.f + expf(-v));
            g_h2[(b * PP + co) * TT + t0 + tl * 4 + n] = v;
        }
    }
}

// ---------------- K2c: predictor p2 conv (jumps) ----------------
__global__ __launch_bounds__(256) void k_p2(const float* __restrict__ p2w,
                                            const float* __restrict__ p2b) {
    int b = blockIdx.y, t0 = blockIdx.x * 256, tid = threadIdx.x;
    __shared__ float hs[PP][270];
    for (int i = tid; i < PP * 270; i += 256) {
        int ci = i / 270, tt = i % 270;
        int gt = t0 - 7 + tt;
        hs[ci][tt] = (gt >= 0 && gt < TT) ? g_h2[(b * PP + ci) * TT + gt] : 0.f;
    }
    __syncthreads();
    float a0 = p2b[0], a1 = p2b[1];
    for (int ci = 0; ci < PP; ++ci) {
#pragma unroll
        for (int k = 0; k < 15; k++) {
            float hv = hs[ci][tid + k];
            a0 += p2w[ci * 15 + k] * hv;
            a1 += p2w[480 + ci * 15 + k] * hv;
        }
    }
    g_jmp[(b * 2 + 0) * TT + t0 + tid] = a0;
    g_jmp[(b * 2 + 1) * TT + t0 + tid] = a1;
}

// ---------------- K3: sigmoid, renorm, double-precision cumsum, boundaries ----------------
__global__ __launch_bounds__(1024) void k_scan(const float* __restrict__ norm_mean) {
    int b = blockIdx.x, tid = threadIdx.x;
    __shared__ double ssum[1024];
    __shared__ int fiS[TT];
    float nm = *norm_mean;
    int t0 = tid * 4;
    float w_[4]; double mo[4], pre[4];
#pragma unroll
    for (int i = 0; i < 4; i++) {
        float j0 = g_jmp[(b * 2 + 0) * TT + t0 + i];
        float j1 = g_jmp[(b * 2 + 1) * TT + t0 + i];
        w_[i] = 1.f / (1.f + expf(-j0));
        mo[i] = (double)(nm / (1.f + expf(-j1)));
    }
    pre[0] = mo[0]; pre[1] = pre[0] + mo[1]; pre[2] = pre[1] + mo[2]; pre[3] = pre[2] + mo[3];
    ssum[tid] = pre[3];
    __syncthreads();
    for (int off = 1; off < 1024; off <<= 1) {
        double v = (tid >= off) ? ssum[tid - off] : 0.0;
        __syncthreads();
        ssum[tid] += v;
        __syncthreads();
    }
    double total = ssum[1023];
    double excl = (tid > 0) ? ssum[tid - 1] : 0.0;
    double renorm = total / (double)TT;
    if (renorm < 1.0) renorm = 1.0;
    double inv = 1.0 / renorm;
#pragma unroll
    for (int i = 0; i < 4; i++) {
        double pos = (excl + pre[i]) * inv;
        double fl = floor(pos);
        float frac = (float)(pos - fl);
        g_c1[b * TT + t0 + i] = w_[i] * (1.f - frac);
        g_c2[b * TT + t0 + i] = w_[i] * frac;
        fiS[t0 + i] = (int)fl;
    }
    __syncthreads();
    int base = b * 4100;
#pragma unroll
    for (int i = 0; i < 4; i++) {
        int t = t0 + i;
        int fp = (t == 0) ? -1 : fiS[t - 1];
        int fc = fiS[t];
        for (int p = fp + 1; p <= fc; p++) g_S[base + p] = t;
    }
    int flast = fiS[TT - 1];
    for (int p = flast + 1 + tid; p <= LL; p += 1024) g_S[base + p] = TT;
}

// ---------------- K4: deterministic gather (replaces scatter-add) ----------------
__global__ __launch_bounds__(256) void k_gather() {
    int b = blockIdx.y;
    int p = blockIdx.x * 4 + (threadIdx.x >> 6);
    int cth = threadIdx.x & 63;
    if (p >= LL) return;
    int base = b * 4100;
    int s0 = (p > 0) ? g_S[base + p - 1] : 0;
    int s1 = g_S[base + p];
    int s2 = g_S[base + p + 1];
    const float4* f4 = (const float4*)g_feat;
    float4 acc = {0.f, 0.f, 0.f, 0.f};
    for (int t = s1; t < s2; ++t) {
        float c = g_c1[b * TT + t];
        float4 v = f4[(size_t)(b * TT + t) * 64 + cth];
        acc.x += c * v.x; acc.y += c * v.y; acc.z += c * v.z; acc.w += c * v.w;
    }
    for (int t = s0; t < s1; ++t) {
        float c = g_c2[b * TT + t];
        float4 v = f4[(size_t)(b * TT + t) * 64 + cth];
        acc.x += c * v.x; acc.y += c * v.y; acc.z += c * v.z; acc.w += c * v.w;
    }
    ((float4*)g_out2)[(size_t)(b * LL + p) * 64 + cth] = acc;
}

// ---------------- K5: transpose (B,L,C) -> (B,C,LPAD) with zero pad ----------------
__global__ void k_transpose(float* __restrict__ out) {
    __shared__ float tile[32][33];
    int b = blockIdx.z;
    int c0 = blockIdx.y * 32, p0 = blockIdx.x * 32;
    int tx = threadIdx.x, ty = threadIdx.y;
    int pin = p0 + ty;
    float v = 0.f;
    if (pin < LL) v = g_out2[((size_t)(b * LL + pin)) * CC + c0 + tx];
    tile[ty][tx] = v;
    __syncthreads();
    int p = p0 + tx;
    if (p < LPAD) out[((size_t)(b * CC + c0 + ty)) * LPAD + p] = tile[tx][ty];
}

// ---------------- launch ----------------
extern "C" void kernel_launch(void* const* d_in, const int* in_sizes, int n_in,
                              void* d_out, int out_size) {
    const float* x       = (const float*)d_in[0];
    const float* conv1_w = (const float*)d_in[1];
    const float* bn1_g   = (const float*)d_in[2];
    const float* bn1_b   = (const float*)d_in[3];
    const float* bn1_m   = (const float*)d_in[4];
    const float* bn1_v   = (const float*)d_in[5];
    const float* w1x1    = (const float*)d_in[6];
    const float* p0_w    = (const float*)d_in[7];
    const float* p0_b    = (const float*)d_in[8];
    const float* p0bn_g  = (const float*)d_in[9];
    const float* p0bn_b  = (const float*)d_in[10];
    const float* p0bn_m  = (const float*)d_in[11];
    const float* p0bn_v  = (const float*)d_in[12];
    const float* p1_w    = (const float*)d_in[13];
    const float* p1_b    = (const float*)d_in[14];
    const float* p1bn_g  = (const float*)d_in[15];
    const float* p1bn_b  = (const float*)d_in[16];
    const float* p1bn_m  = (const float*)d_in[17];
    const float* p1bn_v  = (const float*)d_in[18];
    const float* p2_w    = (const float*)d_in[19];
    const float* p2_b    = (const float*)d_in[20];
    const float* norm_mean = (const float*)d_in[21];
    float* out = (float*)d_out;

    k_fold<<<1, 512>>>(conv1_w, bn1_g, bn1_b, bn1_m, bn1_v,
                       p0_w, p0_b, p0bn_g, p0bn_b, p0bn_m, p0bn_v,
                       p1_w, p1_b, p1bn_g, p1bn_b, p1bn_m, p1bn_v);
    k_gemm<<<dim3((NB * TT) / 64, 4), 256>>>(x, w1x1);
    k_p0<<<dim3(TT / 256, NB), 256>>>();
    k_p1<<<dim3(TT / 128, NB), 256>>>();
    k_p2<<<dim3(TT / 256, NB), 256>>>(p2_w, p2_b);
    k_scan<<<NB, 1024>>>(norm_mean);
    k_gather<<<dim3((LL + 3) / 4, NB), 256>>>();
    k_transpose<<<dim3((LPAD + 31) / 32, CC / 32, NB), dim3(32, 32)>>>(out);
}